// round 1
// baseline (speedup 1.0000x reference)
#include <cuda_runtime.h>
#include <math.h>

#define NROI 512
#define NPOS 128
#define NCLS 81
#define KDIM 12544   // 256*49
#define HID  1024

// ---------------- scratch (device globals; no allocs allowed) ----------------
__device__ float g_featT[17408000];            // transposed FPN maps, (H,W,C) per level
__device__ float g_x[NROI * KDIM];             // pooled features, layout [n][bin][c]
__device__ float g_h1[NROI * HID];
__device__ float g_h2[NROI * HID];
__device__ float g_logits[NROI * NCLS];
__device__ float g_locp[NROI * NCLS * 4];

// ---------------- transpose (C,H,W) -> (H,W,C) ----------------
__global__ void transpose_kernel(const float* __restrict__ src, float* __restrict__ dst,
                                 int H, int W) {
    __shared__ float s[32][33];
    int x = blockIdx.x * 32 + threadIdx.x;   // W divisible by 32 for all levels
    int y = blockIdx.y;
    int c = blockIdx.z * 32 + threadIdx.y;   // C=256 divisible by 32
    s[threadIdx.y][threadIdx.x] = src[(c * H + y) * W + x];
    __syncthreads();
    int c2 = blockIdx.z * 32 + threadIdx.x;
    int x2 = blockIdx.x * 32 + threadIdx.y;
    dst[(y * W + x2) * 256 + c2] = s[threadIdx.x][threadIdx.y];
}

// ---------------- RoIAlign ----------------
// grid (49, 512), block 256 (one thread per channel)
__global__ void pool_kernel(const float* __restrict__ rois,
                            const float* __restrict__ featT,
                            float* __restrict__ xout) {
    int n   = blockIdx.y;
    int bin = blockIdx.x;
    int c   = threadIdx.x;
    int oy = bin / 7, ox = bin % 7;

    float rx1 = rois[n * 4 + 0], ry1 = rois[n * 4 + 1];
    float rx2 = rois[n * 4 + 2], ry2 = rois[n * 4 + 3];

    // level assignment
    float area = (rx2 - rx1 + 1.0f) * (ry2 - ry1 + 1.0f);
    float lf = floorf(4.0f + log2f(sqrtf(area) / 224.0f));
    lf = fminf(fmaxf(lf, 2.0f), 5.0f);
    int lv = (int)lf - 2;

    const int   Hs[4]    = {200, 100, 50, 25};
    const int   Ws[4]    = {256, 128, 64, 32};
    const int   bases[4] = {0, 13107200, 16384000, 17203200};
    const float scl[4]   = {0.25f, 0.125f, 0.0625f, 0.03125f};

    int H = Hs[lv], W = Ws[lv];
    const float* ft = featT + bases[lv];
    float scale = scl[lv];

    float x1 = rx1 * scale, y1 = ry1 * scale;
    float x2 = rx2 * scale, y2 = ry2 * scale;
    float bw = fmaxf(x2 - x1, 1.0f) / 7.0f;
    float bh = fmaxf(y2 - y1, 1.0f) / 7.0f;

    float acc = 0.0f;
    #pragma unroll
    for (int sy = 0; sy < 2; sy++) {
        #pragma unroll
        for (int sx = 0; sx < 2; sx++) {
            float px = x1 + ((float)ox + ((float)sx + 0.5f) * 0.5f) * bw;
            float py = y1 + ((float)oy + ((float)sy + 0.5f) * 0.5f) * bh;
            bool valid = (px > -1.0f) && (px < (float)W) && (py > -1.0f) && (py < (float)H);
            if (!valid) continue;
            float xx = fminf(fmaxf(px, 0.0f), (float)(W - 1));
            float yy = fminf(fmaxf(py, 0.0f), (float)(H - 1));
            float x0f = floorf(xx), y0f = floorf(yy);
            float lx = xx - x0f, ly = yy - y0f;
            int x0 = (int)x0f, y0 = (int)y0f;
            int x1i = min(x0 + 1, W - 1), y1i = min(y0 + 1, H - 1);
            const float* r0 = ft + (size_t)(y0  * W) * 256;
            const float* r1 = ft + (size_t)(y1i * W) * 256;
            float w00 = (1.0f - ly) * (1.0f - lx);
            float w01 = (1.0f - ly) * lx;
            float w10 = ly * (1.0f - lx);
            float w11 = ly * lx;
            acc += w00 * r0[x0 * 256 + c] + w01 * r0[x1i * 256 + c]
                 + w10 * r1[x0 * 256 + c] + w11 * r1[x1i * 256 + c];
        }
    }
    // layout [n][bin][c]; GEMM1 permutes W1 rows to compensate (k = c*49 + bin)
    xout[n * KDIM + bin * 256 + c] = acc * 0.25f;
}

// ---------------- generic SGEMM: C = op(A[M,K] @ B[K,N] + bias) ----------------
// PERM=1: B row index r = (k%256)*49 + k/256  (maps k'=bin*256+c to W1 row c*49+bin)
template <bool RELU, int PERM>
__global__ void sgemm_kernel(const float* __restrict__ A, const float* __restrict__ B,
                             const float* __restrict__ bias, float* __restrict__ C,
                             int M, int N, int K) {
    const int BM = 64, BN = 64, BK = 16;
    __shared__ float As[BK][BM + 1];
    __shared__ float Bs[BK][BN];

    int tid = threadIdx.x;          // 256 threads
    int m0 = blockIdx.y * BM;
    int n0 = blockIdx.x * BN;
    int ty = tid / 16, tx = tid % 16;

    float acc[4][4];
    #pragma unroll
    for (int i = 0; i < 4; i++)
        #pragma unroll
        for (int j = 0; j < 4; j++) acc[i][j] = 0.0f;

    for (int k0 = 0; k0 < K; k0 += BK) {
        #pragma unroll
        for (int i = tid; i < BM * BK; i += 256) {
            int m = i / BK, kk = i % BK;
            As[kk][m] = A[(size_t)(m0 + m) * K + k0 + kk];
        }
        #pragma unroll
        for (int i = tid; i < BK * BN; i += 256) {
            int kk = i / BN, nn = i % BN;
            int kg = k0 + kk;
            int r = PERM ? ((kg & 255) * 49 + (kg >> 8)) : kg;
            Bs[kk][nn] = (n0 + nn < N) ? B[(size_t)r * N + n0 + nn] : 0.0f;
        }
        __syncthreads();
        #pragma unroll
        for (int kk = 0; kk < BK; kk++) {
            float a[4], b[4];
            #pragma unroll
            for (int i = 0; i < 4; i++) a[i] = As[kk][ty * 4 + i];
            #pragma unroll
            for (int j = 0; j < 4; j++) b[j] = Bs[kk][tx * 4 + j];
            #pragma unroll
            for (int i = 0; i < 4; i++)
                #pragma unroll
                for (int j = 0; j < 4; j++) acc[i][j] += a[i] * b[j];
        }
        __syncthreads();
    }

    #pragma unroll
    for (int i = 0; i < 4; i++) {
        int m = m0 + ty * 4 + i;
        #pragma unroll
        for (int j = 0; j < 4; j++) {
            int n = n0 + tx * 4 + j;
            if (n < N) {
                float v = acc[i][j] + bias[n];
                if (RELU) v = fmaxf(v, 0.0f);
                C[(size_t)m * N + n] = v;
            }
        }
    }
}

// ---------------- loss: softmax-CE + smooth-L1 ----------------
__global__ void loss_kernel(const float* __restrict__ logits, const float* __restrict__ locp,
                            const int* __restrict__ label, const float* __restrict__ loc,
                            float* __restrict__ out) {
    __shared__ float red[512];
    int n = threadIdx.x;
    const float* lg = logits + n * NCLS;

    float mx = -1e30f;
    for (int j = 0; j < NCLS; j++) mx = fmaxf(mx, lg[j]);
    float s = 0.0f;
    for (int j = 0; j < NCLS; j++) s += expf(lg[j] - mx);
    int lab = label[n];
    float logp = lg[lab] - mx - logf(s);
    float contrib = -logp * (1.0f / (float)NROI);

    if (n < NPOS) {
        #pragma unroll
        for (int j = 0; j < 4; j++) {
            float d = fabsf(locp[n * (NCLS * 4) + lab * 4 + j] - loc[n * 4 + j]);
            float sl1 = (d < 1.0f) ? 0.5f * d * d : d - 0.5f;
            contrib += sl1 * (1.0f / (float)NROI);
        }
    }
    red[n] = contrib;
    __syncthreads();
    for (int stride = 256; stride > 0; stride >>= 1) {
        if (n < stride) red[n] += red[n + stride];
        __syncthreads();
    }
    if (n == 0) out[0] = red[0];
}

// ---------------- launch ----------------
extern "C" void kernel_launch(void* const* d_in, const int* in_sizes, int n_in,
                              void* d_out, int out_size) {
    const float* P[4]  = {(const float*)d_in[0], (const float*)d_in[1],
                          (const float*)d_in[2], (const float*)d_in[3]};
    const float* rois  = (const float*)d_in[4];
    const int*   label = (const int*)  d_in[5];
    const float* loc   = (const float*)d_in[6];
    const float* W1    = (const float*)d_in[7];
    const float* b1    = (const float*)d_in[8];
    const float* W2    = (const float*)d_in[9];
    const float* b2    = (const float*)d_in[10];
    const float* Wcls  = (const float*)d_in[11];
    const float* bcls  = (const float*)d_in[12];
    const float* Wloc  = (const float*)d_in[13];
    const float* bloc  = (const float*)d_in[14];
    float* out = (float*)d_out;

    float *featT, *xb, *h1, *h2, *logits, *locp;
    cudaGetSymbolAddress((void**)&featT,  g_featT);
    cudaGetSymbolAddress((void**)&xb,     g_x);
    cudaGetSymbolAddress((void**)&h1,     g_h1);
    cudaGetSymbolAddress((void**)&h2,     g_h2);
    cudaGetSymbolAddress((void**)&logits, g_logits);
    cudaGetSymbolAddress((void**)&locp,   g_locp);

    const int Hs[4] = {200, 100, 50, 25};
    const int Ws[4] = {256, 128, 64, 32};
    int base = 0;
    for (int l = 0; l < 4; l++) {
        dim3 g(Ws[l] / 32, Hs[l], 8);
        transpose_kernel<<<g, dim3(32, 32)>>>(P[l], featT + base, Hs[l], Ws[l]);
        base += Hs[l] * Ws[l] * 256;
    }

    pool_kernel<<<dim3(49, NROI), 256>>>(rois, featT, xb);

    // FC1: relu(x @ W1 + b1), with W1 row permutation
    sgemm_kernel<true, 1><<<dim3(HID / 64, NROI / 64), 256>>>(xb, W1, b1, h1, NROI, HID, KDIM);
    // FC2
    sgemm_kernel<true, 0><<<dim3(HID / 64, NROI / 64), 256>>>(h1, W2, b2, h2, NROI, HID, HID);
    // heads
    sgemm_kernel<false, 0><<<dim3(2, NROI / 64), 256>>>(h2, Wcls, bcls, logits, NROI, NCLS, HID);
    sgemm_kernel<false, 0><<<dim3(6, NROI / 64), 256>>>(h2, Wloc, bloc, locp, NROI, NCLS * 4, HID);

    loss_kernel<<<1, 512>>>(logits, locp, label, loc, out);
}

// round 3
// speedup vs baseline: 7.7380x; 7.7380x over previous
#include <cuda_runtime.h>
#include <cuda_fp16.h>
#include <math.h>
#include <stdint.h>

#define NROI 512
#define NPOS 128
#define NCLS 81
#define KDIM 12544   // 256*49
#define HID  1024
#define NHEAD 448    // 81 + 324 padded to 64-multiple

// ---------------- scratch (device globals; no allocs allowed) ----------------
__device__ __align__(256) __half g_featT[17408000];      // (H,W,C) fp16 FPN maps
__device__ __align__(256) __half g_x[NROI * KDIM];       // pooled, [n][bin*256+c]
__device__ __align__(256) __half g_W1T[HID * KDIM];      // K-major, permuted rows
__device__ __align__(256) __half g_W2T[HID * HID];
__device__ __align__(256) __half g_WhT[NHEAD * HID];
__device__ float g_bh[NHEAD];
__device__ __align__(256) __half g_h1[NROI * HID];
__device__ __align__(256) __half g_h2[NROI * HID];
__device__ float g_head[NROI * NHEAD];
__device__ float g_part[2 * NROI * HID];                 // split-K partials (max 2*512*1024)

// ---------------- helpers ----------------
__device__ __forceinline__ uint32_t smem_u32(const void* p) {
    uint32_t a;
    asm("{ .reg .u64 t; cvta.to.shared.u64 t, %1; cvt.u32.u64 %0, t; }" : "=r"(a) : "l"(p));
    return a;
}
#define CP_ASYNC16(dst, src) asm volatile("cp.async.cg.shared.global [%0], [%1], 16;" :: "r"(dst), "l"(src))
#define CP_COMMIT() asm volatile("cp.async.commit_group;" ::: "memory")
#define CP_WAIT(n)  asm volatile("cp.async.wait_group %0;" :: "n"(n) : "memory")

#define LDSM_X4(r0, r1, r2, r3, a) \
    asm volatile("ldmatrix.sync.aligned.m8n8.x4.shared.b16 {%0,%1,%2,%3}, [%4];" \
        : "=r"(r0), "=r"(r1), "=r"(r2), "=r"(r3) : "r"(a))

#define MMA16816(d, a, b0, b1) \
    asm volatile("mma.sync.aligned.m16n8k16.row.col.f32.f16.f16.f32 " \
        "{%0,%1,%2,%3}, {%4,%5,%6,%7}, {%8,%9}, {%0,%1,%2,%3};" \
        : "+f"((d)[0]), "+f"((d)[1]), "+f"((d)[2]), "+f"((d)[3]) \
        : "r"((a)[0]), "r"((a)[1]), "r"((a)[2]), "r"((a)[3]), "r"(b0), "r"(b1))

// ---------------- transpose (C,H,W) -> (H,W,C) fp16 ----------------
__global__ void transpose_kernel(const float* __restrict__ src, __half* __restrict__ dst,
                                 int H, int W) {
    __shared__ float s[32][33];
    int x = blockIdx.x * 32 + threadIdx.x;
    int y = blockIdx.y;
    int c = blockIdx.z * 32 + threadIdx.y;
    s[threadIdx.y][threadIdx.x] = src[(c * H + y) * W + x];
    __syncthreads();
    int c2 = blockIdx.z * 32 + threadIdx.x;
    int x2 = blockIdx.x * 32 + threadIdx.y;
    dst[(size_t)(y * W + x2) * 256 + c2] = __float2half(s[threadIdx.x][threadIdx.y]);
}

// ---------------- weight prep ----------------
// W1T[j][k'] = W1[(k'%256)*49 + k'/256][j]
__global__ void w1t_kernel(const float* __restrict__ W1, __half* __restrict__ W1T) {
    __shared__ float s[32][33];
    int kp0 = blockIdx.x * 32;
    int j0  = blockIdx.y * 32;
    int kk = kp0 + threadIdx.y;
    int r = (kk & 255) * 49 + (kk >> 8);
    s[threadIdx.y][threadIdx.x] = W1[(size_t)r * HID + j0 + threadIdx.x];
    __syncthreads();
    W1T[(size_t)(j0 + threadIdx.y) * KDIM + kp0 + threadIdx.x] =
        __float2half(s[threadIdx.x][threadIdx.y]);
}

__global__ void w2t_kernel(const float* __restrict__ W2, __half* __restrict__ W2T) {
    __shared__ float s[32][33];
    int k0 = blockIdx.x * 32;
    int j0 = blockIdx.y * 32;
    s[threadIdx.y][threadIdx.x] = W2[(size_t)(k0 + threadIdx.y) * HID + j0 + threadIdx.x];
    __syncthreads();
    W2T[(size_t)(j0 + threadIdx.y) * HID + k0 + threadIdx.x] =
        __float2half(s[threadIdx.x][threadIdx.y]);
}

__global__ void whead_kernel(const float* __restrict__ Wcls, const float* __restrict__ Wloc,
                             __half* __restrict__ WhT) {
    int j = blockIdx.y;
    int k = blockIdx.x * 256 + threadIdx.x;
    float v = 0.0f;
    if (j < NCLS) v = Wcls[(size_t)k * NCLS + j];
    else if (j < NCLS * 5) v = Wloc[(size_t)k * (NCLS * 4) + (j - NCLS)];
    WhT[(size_t)j * HID + k] = __float2half(v);
}

__global__ void bhead_kernel(const float* __restrict__ bcls, const float* __restrict__ bloc,
                             float* __restrict__ bh) {
    int j = threadIdx.x;
    if (j < NHEAD) {
        float v = 0.0f;
        if (j < NCLS) v = bcls[j];
        else if (j < NCLS * 5) v = bloc[j - NCLS];
        bh[j] = v;
    }
}

// ---------------- RoIAlign ----------------
__global__ void pool_kernel(const float* __restrict__ rois,
                            const __half* __restrict__ featT,
                            __half* __restrict__ xout) {
    int n = blockIdx.y, bin = blockIdx.x, c = threadIdx.x;
    int oy = bin / 7, ox = bin % 7;

    float rx1 = rois[n * 4 + 0], ry1 = rois[n * 4 + 1];
    float rx2 = rois[n * 4 + 2], ry2 = rois[n * 4 + 3];
    float area = (rx2 - rx1 + 1.0f) * (ry2 - ry1 + 1.0f);
    float lf = floorf(4.0f + log2f(sqrtf(area) / 224.0f));
    lf = fminf(fmaxf(lf, 2.0f), 5.0f);
    int lv = (int)lf - 2;

    const int   Hs[4]    = {200, 100, 50, 25};
    const int   Ws[4]    = {256, 128, 64, 32};
    const int   bases[4] = {0, 13107200, 16384000, 17203200};
    const float scl[4]   = {0.25f, 0.125f, 0.0625f, 0.03125f};

    int H = Hs[lv], W = Ws[lv];
    const __half* ft = featT + bases[lv];
    float scale = scl[lv];

    float x1 = rx1 * scale, y1 = ry1 * scale;
    float x2 = rx2 * scale, y2 = ry2 * scale;
    float bw = fmaxf(x2 - x1, 1.0f) / 7.0f;
    float bh = fmaxf(y2 - y1, 1.0f) / 7.0f;

    float acc = 0.0f;
    #pragma unroll
    for (int sy = 0; sy < 2; sy++) {
        #pragma unroll
        for (int sx = 0; sx < 2; sx++) {
            float px = x1 + ((float)ox + ((float)sx + 0.5f) * 0.5f) * bw;
            float py = y1 + ((float)oy + ((float)sy + 0.5f) * 0.5f) * bh;
            bool valid = (px > -1.0f) && (px < (float)W) && (py > -1.0f) && (py < (float)H);
            if (!valid) continue;
            float xx = fminf(fmaxf(px, 0.0f), (float)(W - 1));
            float yy = fminf(fmaxf(py, 0.0f), (float)(H - 1));
            float x0f = floorf(xx), y0f = floorf(yy);
            float lx = xx - x0f, ly = yy - y0f;
            int x0 = (int)x0f, y0 = (int)y0f;
            int x1i = min(x0 + 1, W - 1), y1i = min(y0 + 1, H - 1);
            const __half* r0 = ft + (size_t)(y0  * W) * 256;
            const __half* r1 = ft + (size_t)(y1i * W) * 256;
            float w00 = (1.0f - ly) * (1.0f - lx);
            float w01 = (1.0f - ly) * lx;
            float w10 = ly * (1.0f - lx);
            float w11 = ly * lx;
            acc += w00 * __half2float(r0[x0 * 256 + c]) + w01 * __half2float(r0[x1i * 256 + c])
                 + w10 * __half2float(r1[x0 * 256 + c]) + w11 * __half2float(r1[x1i * 256 + c]);
        }
    }
    xout[(size_t)n * KDIM + bin * 256 + c] = __float2half(acc * 0.25f);
}

// ---------------- HMMA GEMM: part[z][M][N] = A[M, z-slice of K] @ Bt[N, K]^T ----------------
// BM=128, BN=64, BK=32. 256 threads = 8 warps (4 m x 2 n), warp tile 32x32.
// SMEM rows of 32 halves (64B), 16B chunks swizzled: c ^= (row>>1)&3.
__global__ void __launch_bounds__(256) gemm_hmma(const __half* __restrict__ A,
                                                 const __half* __restrict__ Bt,
                                                 float* __restrict__ part,
                                                 int N, int Krow, int ksplit) {
    __shared__ __align__(128) __half As[2][128 * 32];
    __shared__ __align__(128) __half Bs[2][64 * 32];

    int tid = threadIdx.x, wid = tid >> 5, lane = tid & 31;
    int m0 = blockIdx.y * 128, n0 = blockIdx.x * 64;
    int z = blockIdx.z;
    int kb0 = z * ksplit;
    int wm = (wid & 3) * 32;       // warp m offset in tile
    int wn = (wid >> 2) * 32;      // warp n offset in tile

    uint32_t sA = smem_u32(As), sB = smem_u32(Bs);
    int nch = ksplit >> 5;

    // store offsets (halves): row*32 + swz(chunk)*8
    int ldr = tid >> 2, ldc = tid & 3;

    // prefetch chunk 0
    {
        #pragma unroll
        for (int i = 0; i < 2; i++) {
            int row = ldr + i * 64;
            int sw = (ldc ^ ((row >> 1) & 3));
            CP_ASYNC16(sA + (row * 32 + sw * 8) * 2,
                       (const char*)(A + (size_t)(m0 + row) * Krow + kb0) + ldc * 16);
        }
        {
            int row = ldr;
            int sw = (ldc ^ ((row >> 1) & 3));
            CP_ASYNC16(sB + (row * 32 + sw * 8) * 2,
                       (const char*)(Bt + (size_t)(n0 + row) * Krow + kb0) + ldc * 16);
        }
        CP_COMMIT();
    }

    float acc[2][4][4];
    #pragma unroll
    for (int mi = 0; mi < 2; mi++)
        #pragma unroll
        for (int ni = 0; ni < 4; ni++)
            #pragma unroll
            for (int j = 0; j < 4; j++) acc[mi][ni][j] = 0.0f;

    for (int k = 0; k < nch; k++) {
        int buf = k & 1;
        if (k + 1 < nch) {
            int b = 1 - buf;
            int kg = kb0 + ((k + 1) << 5);
            #pragma unroll
            for (int i = 0; i < 2; i++) {
                int row = ldr + i * 64;
                int sw = (ldc ^ ((row >> 1) & 3));
                CP_ASYNC16(sA + (b * 4096 + row * 32 + sw * 8) * 2,
                           (const char*)(A + (size_t)(m0 + row) * Krow + kg) + ldc * 16);
            }
            {
                int row = ldr;
                int sw = (ldc ^ ((row >> 1) & 3));
                CP_ASYNC16(sB + (b * 2048 + row * 32 + sw * 8) * 2,
                           (const char*)(Bt + (size_t)(n0 + row) * Krow + kg) + ldc * 16);
            }
            CP_COMMIT();
            CP_WAIT(1);
        } else {
            CP_WAIT(0);
        }
        __syncthreads();

        // B fragments: 4 n8-frags, each ldmatrix.x4 covers k0..31
        uint32_t bf[4][4];
        #pragma unroll
        for (int ni = 0; ni < 4; ni++) {
            int row = wn + ni * 8 + (lane & 7);
            int ch = lane >> 3;
            int sw = ch ^ ((row >> 1) & 3);
            uint32_t a = sB + (buf * 2048 + row * 32 + sw * 8) * 2;
            LDSM_X4(bf[ni][0], bf[ni][1], bf[ni][2], bf[ni][3], a);
        }
        // k-steps
        #pragma unroll
        for (int s = 0; s < 2; s++) {
            uint32_t af[2][4];
            #pragma unroll
            for (int mi = 0; mi < 2; mi++) {
                int row = wm + mi * 16 + (lane & 15);
                int ch = 2 * s + (lane >> 4);
                int sw = ch ^ ((row >> 1) & 3);
                uint32_t a = sA + (buf * 4096 + row * 32 + sw * 8) * 2;
                LDSM_X4(af[mi][0], af[mi][1], af[mi][2], af[mi][3], a);
            }
            #pragma unroll
            for (int mi = 0; mi < 2; mi++)
                #pragma unroll
                for (int ni = 0; ni < 4; ni++)
                    MMA16816(acc[mi][ni], af[mi], bf[ni][2 * s], bf[ni][2 * s + 1]);
        }
        __syncthreads();
    }

    // epilogue: fp32 partials
    float* out = part + (size_t)z * NROI * N;
    #pragma unroll
    for (int mi = 0; mi < 2; mi++) {
        #pragma unroll
        for (int ni = 0; ni < 4; ni++) {
            int m = m0 + wm + mi * 16 + (lane >> 2);
            int n = n0 + wn + ni * 8 + (lane & 3) * 2;
            out[(size_t)m * N + n]           = acc[mi][ni][0];
            out[(size_t)m * N + n + 1]       = acc[mi][ni][1];
            out[(size_t)(m + 8) * N + n]     = acc[mi][ni][2];
            out[(size_t)(m + 8) * N + n + 1] = acc[mi][ni][3];
        }
    }
}

// ---------------- combine: out = act(sum_z part + bias) ----------------
template <int SPLIT, bool RELU, bool HOUT>
__global__ void combine_kernel(const float* __restrict__ part, const float* __restrict__ bias,
                               void* __restrict__ out, int N) {
    int idx = blockIdx.x * 256 + threadIdx.x;
    int MN = NROI * N;
    if (idx >= MN) return;
    int n = idx % N;
    float v = bias[n] + part[idx];
    if (SPLIT == 2) v += part[MN + idx];
    if (RELU) v = fmaxf(v, 0.0f);
    if (HOUT) ((__half*)out)[idx] = __float2half(v);
    else      ((float*)out)[idx] = v;
}

// ---------------- loss ----------------
__global__ void loss_kernel(const float* __restrict__ head,
                            const int* __restrict__ label, const float* __restrict__ loc,
                            float* __restrict__ out) {
    __shared__ float red[512];
    int n = threadIdx.x;
    const float* lg = head + (size_t)n * NHEAD;

    float mx = -1e30f;
    for (int j = 0; j < NCLS; j++) mx = fmaxf(mx, lg[j]);
    float s = 0.0f;
    for (int j = 0; j < NCLS; j++) s += expf(lg[j] - mx);
    int lab = label[n];
    float logp = lg[lab] - mx - logf(s);
    float contrib = -logp * (1.0f / (float)NROI);

    if (n < NPOS) {
        #pragma unroll
        for (int j = 0; j < 4; j++) {
            float d = fabsf(head[(size_t)n * NHEAD + NCLS + lab * 4 + j] - loc[n * 4 + j]);
            float sl1 = (d < 1.0f) ? 0.5f * d * d : d - 0.5f;
            contrib += sl1 * (1.0f / (float)NROI);
        }
    }
    red[n] = contrib;
    __syncthreads();
    for (int stride = 256; stride > 0; stride >>= 1) {
        if (n < stride) red[n] += red[n + stride];
        __syncthreads();
    }
    if (n == 0) out[0] = red[0];
}

// ---------------- launch ----------------
extern "C" void kernel_launch(void* const* d_in, const int* in_sizes, int n_in,
                              void* d_out, int out_size) {
    const float* P[4]  = {(const float*)d_in[0], (const float*)d_in[1],
                          (const float*)d_in[2], (const float*)d_in[3]};
    const float* rois  = (const float*)d_in[4];
    const int*   label = (const int*)  d_in[5];
    const float* loc   = (const float*)d_in[6];
    const float* W1    = (const float*)d_in[7];
    const float* b1    = (const float*)d_in[8];
    const float* W2    = (const float*)d_in[9];
    const float* b2    = (const float*)d_in[10];
    const float* Wcls  = (const float*)d_in[11];
    const float* bcls  = (const float*)d_in[12];
    const float* Wloc  = (const float*)d_in[13];
    const float* bloc  = (const float*)d_in[14];
    float* out = (float*)d_out;

    __half *featT, *xb, *w1t, *w2t, *wht, *h1, *h2;
    float *bh, *head, *partb;
    cudaGetSymbolAddress((void**)&featT, g_featT);
    cudaGetSymbolAddress((void**)&xb,    g_x);
    cudaGetSymbolAddress((void**)&w1t,   g_W1T);
    cudaGetSymbolAddress((void**)&w2t,   g_W2T);
    cudaGetSymbolAddress((void**)&wht,   g_WhT);
    cudaGetSymbolAddress((void**)&bh,    g_bh);
    cudaGetSymbolAddress((void**)&h1,    g_h1);
    cudaGetSymbolAddress((void**)&h2,    g_h2);
    cudaGetSymbolAddress((void**)&head,  g_head);
    cudaGetSymbolAddress((void**)&partb, g_part);

    // weight prep
    w1t_kernel<<<dim3(KDIM / 32, HID / 32), dim3(32, 32)>>>(W1, w1t);
    w2t_kernel<<<dim3(HID / 32, HID / 32), dim3(32, 32)>>>(W2, w2t);
    whead_kernel<<<dim3(HID / 256, NHEAD), 256>>>(Wcls, Wloc, wht);
    bhead_kernel<<<1, 512>>>(bcls, bloc, bh);

    // feature transpose to fp16
    const int Hs[4] = {200, 100, 50, 25};
    const int Ws[4] = {256, 128, 64, 32};
    int base = 0;
    for (int l = 0; l < 4; l++) {
        transpose_kernel<<<dim3(Ws[l] / 32, Hs[l], 8), dim3(32, 32)>>>(P[l], featT + base, Hs[l], Ws[l]);
        base += Hs[l] * Ws[l] * 256;
    }

    pool_kernel<<<dim3(49, NROI), 256>>>(rois, featT, xb);

    // FC1 (split-K = 2): relu(x @ W1 + b1) -> h1 fp16
    gemm_hmma<<<dim3(HID / 64, NROI / 128, 2), 256>>>(xb, w1t, partb, HID, KDIM, KDIM / 2);
    combine_kernel<2, true, true><<<(NROI * HID + 255) / 256, 256>>>(partb, b1, h1, HID);

    // FC2: relu(h1 @ W2 + b2) -> h2 fp16
    gemm_hmma<<<dim3(HID / 64, NROI / 128, 1), 256>>>(h1, w2t, partb, HID, HID, HID);
    combine_kernel<1, true, true><<<(NROI * HID + 255) / 256, 256>>>(partb, b2, h2, HID);

    // heads: h2 @ [Wcls|Wloc] -> fp32 [512][448]
    gemm_hmma<<<dim3(NHEAD / 64, NROI / 128, 1), 256>>>(h2, wht, partb, NHEAD, HID, HID);
    combine_kernel<1, false, false><<<(NROI * NHEAD + 255) / 256, 256>>>(partb, bh, head, NHEAD);

    loss_kernel<<<1, 512>>>(head, label, loc, out);
}